// round 2
// baseline (speedup 1.0000x reference)
#include <cuda_runtime.h>
#include <cuda_bf16.h>

#define TLEN  1024
#define NA    6
#define GAMMA 0.98f
#define GL    (0.98f * 0.93f)
#define EPSI  0.2f
#define MAXB  4096

// Per-block partial sums: [ppo | value | entropy], channel stride MAXB.
// Overwritten (not accumulated) every launch -> no zeroing needed, deterministic.
__device__ float g_part[3 * MAXB];

__device__ __forceinline__ float warp_sum(float v) {
#pragma unroll
    for (int o = 16; o; o >>= 1) v += __shfl_xor_sync(0xffffffffu, v, o);
    return v;
}

// One block per batch row b; thread t owns timestep t.
__global__ __launch_bounds__(TLEN) void ppo_main(
    const float* __restrict__ rewards,
    const float* __restrict__ values,
    const float* __restrict__ logits,
    const float* __restrict__ logits_old,
    const int*   __restrict__ dones,      // jnp.bool_ widened to int32 by harness
    const int*   __restrict__ actions)
{
    const int b    = blockIdx.x;
    const int t    = threadIdx.x;
    const int lane = t & 31;
    const int wrp  = t >> 5;
    const long idx = (long)b * TLEN + t;

    const float r  = rewards[idx];
    const float v  = values[idx];
    const bool  d  = dones[idx] != 0;
    const int   act = actions[idx];

    __shared__ float sv[TLEN];
    sv[t] = v;

    // ---- log-softmax gather (6 actions, 3x float2 coalesced loads each) ----
    const float2* L  = reinterpret_cast<const float2*>(logits)     + idx * 3;
    const float2* LO = reinterpret_cast<const float2*>(logits_old) + idx * 3;
    float2 l0 = L[0],  l1 = L[1],  l2 = L[2];
    float2 o0 = LO[0], o1 = LO[1], o2 = LO[2];

    float m = fmaxf(fmaxf(fmaxf(l0.x, l0.y), fmaxf(l1.x, l1.y)), fmaxf(l2.x, l2.y));
    float s = __expf(l0.x - m) + __expf(l0.y - m) + __expf(l1.x - m)
            + __expf(l1.y - m) + __expf(l2.x - m) + __expf(l2.y - m);
    float lse = m + __logf(s);
    float xa = (act == 0) ? l0.x : (act == 1) ? l0.y : (act == 2) ? l1.x
             : (act == 3) ? l1.y : (act == 4) ? l2.x : l2.y;
    float log_pi = xa - lse;

    float mo = fmaxf(fmaxf(fmaxf(o0.x, o0.y), fmaxf(o1.x, o1.y)), fmaxf(o2.x, o2.y));
    float so = __expf(o0.x - mo) + __expf(o0.y - mo) + __expf(o1.x - mo)
             + __expf(o1.y - mo) + __expf(o2.x - mo) + __expf(o2.y - mo);
    float lseo = mo + __logf(so);
    float xao = (act == 0) ? o0.x : (act == 1) ? o0.y : (act == 2) ? o1.x
              : (act == 3) ? o1.y : (act == 4) ? o2.x : o2.y;
    float log_pio = xao - lseo;

    __syncthreads();
    float vnext = (t < TLEN - 1) ? sv[t + 1] : 0.f;

    // ---- affine pairs for the two reverse recurrences ----
    // x_t = bX + aX * x_{t+1}; suffix-compose: (a,b)⊕(a2,b2) = (a*a2, b + a*b2)
    float aR, bR, aA, bA;
    if (t == TLEN - 1) {
        aR = 0.f; bR = d ? r : v;      // last = where(done, reward, value)
        aA = 0.f; bA = 0.f;            // GAE init carry = 0
    } else {
        aR = d ? 0.f : GAMMA;  bR = r;
        aA = d ? 0.f : GL;
        bA = r + GAMMA * (d ? 0.f : vnext) - v;  // td error
    }

    // ---- warp-level Kogge-Stone suffix scan (both recurrences fused) ----
#pragma unroll
    for (int dd = 1; dd < 32; dd <<= 1) {
        float aR2 = __shfl_down_sync(0xffffffffu, aR, dd);
        float bR2 = __shfl_down_sync(0xffffffffu, bR, dd);
        float aA2 = __shfl_down_sync(0xffffffffu, aA, dd);
        float bA2 = __shfl_down_sync(0xffffffffu, bA, dd);
        if (lane + dd < 32) {
            bR = fmaf(aR, bR2, bR); aR *= aR2;
            bA = fmaf(aA, bA2, bA); aA *= aA2;
        }
    }

    // ---- cross-warp stage: exclusive suffix of the 32 warp aggregates ----
    __shared__ float sRa[32], sRb[32], sGa[32], sGb[32];
    if (lane == 0) { sRa[wrp] = aR; sRb[wrp] = bR; sGa[wrp] = aA; sGb[wrp] = bA; }
    __syncthreads();

    if (wrp == 0) {
        float ga = sRa[lane], gb = sRb[lane], ha = sGa[lane], hb = sGb[lane];
#pragma unroll
        for (int dd = 1; dd < 32; dd <<= 1) {
            float ga2 = __shfl_down_sync(0xffffffffu, ga, dd);
            float gb2 = __shfl_down_sync(0xffffffffu, gb, dd);
            float ha2 = __shfl_down_sync(0xffffffffu, ha, dd);
            float hb2 = __shfl_down_sync(0xffffffffu, hb, dd);
            if (lane + dd < 32) {
                gb = fmaf(ga, gb2, gb); ga *= ga2;
                hb = fmaf(ha, hb2, hb); ha *= ha2;
            }
        }
        // exclusive = inclusive of lane+1; identity at lane 31
        float ea = __shfl_down_sync(0xffffffffu, ga, 1);
        float eb = __shfl_down_sync(0xffffffffu, gb, 1);
        float fa = __shfl_down_sync(0xffffffffu, ha, 1);
        float fb = __shfl_down_sync(0xffffffffu, hb, 1);
        if (lane == 31) { ea = 1.f; eb = 0.f; fa = 1.f; fb = 0.f; }
        sRa[lane] = ea; sRb[lane] = eb; sGa[lane] = fa; sGb[lane] = fb;
    }
    __syncthreads();

    const float R = fmaf(aR, sRb[wrp], bR);   // future return at t
    const float A = fmaf(aA, sGb[wrp], bA);   // GAE at t (valid t < T-1)

    // ---- loss contributions ----
    float ent = log_pi;
    float dv  = R - v;
    float vt  = dv * dv;
    float pt  = 0.f;
    if (t < TLEN - 1) {
        float ratio = __expf(log_pi - log_pio);
        // clip(r, 1-eps, eps) with 1-eps > eps collapses to constant eps
        pt = fminf(ratio * A, EPSI * A);
    }

    pt = warp_sum(pt); vt = warp_sum(vt); ent = warp_sum(ent);
    __shared__ float r0[32], r1[32], r2[32];
    if (lane == 0) { r0[wrp] = pt; r1[wrp] = vt; r2[wrp] = ent; }
    __syncthreads();
    if (wrp == 0) {
        float a0 = warp_sum(r0[lane]);
        float a1 = warp_sum(r1[lane]);
        float a2 = warp_sum(r2[lane]);
        if (lane == 0) {
            g_part[b]            = a0;
            g_part[MAXB + b]     = a1;
            g_part[2 * MAXB + b] = a2;
        }
    }
}

__global__ __launch_bounds__(1024) void ppo_finalize(float* __restrict__ out, int B)
{
    const int t = threadIdx.x, lane = t & 31, wrp = t >> 5;
    float s0 = 0.f, s1 = 0.f, s2 = 0.f;
    for (int i = t; i < B; i += blockDim.x) {
        s0 += g_part[i];
        s1 += g_part[MAXB + i];
        s2 += g_part[2 * MAXB + i];
    }
    s0 = warp_sum(s0); s1 = warp_sum(s1); s2 = warp_sum(s2);
    __shared__ float r0[32], r1[32], r2[32];
    if (lane == 0) { r0[wrp] = s0; r1[wrp] = s1; r2[wrp] = s2; }
    __syncthreads();
    if (wrp == 0) {
        float a0 = warp_sum(r0[lane]);
        float a1 = warp_sum(r1[lane]);
        float a2 = warp_sum(r2[lane]);
        if (lane == 0) {
            double nBT  = (double)B * TLEN;
            double nBT1 = (double)B * (TLEN - 1);
            out[0] = (float)(-(double)a0 / nBT1);  // ppo_loss
            out[1] = (float)( (double)a1 / nBT);   // value_loss
            out[2] = (float)(-(double)a2 / nBT);   // entropy_loss
        }
    }
}

extern "C" void kernel_launch(void* const* d_in, const int* in_sizes, int n_in,
                              void* d_out, int out_size)
{
    const float* rewards    = (const float*)d_in[0];
    const float* values     = (const float*)d_in[1];
    const float* logits     = (const float*)d_in[2];
    const float* logits_old = (const float*)d_in[3];
    const int*   dones      = (const int*)d_in[4];
    const int*   actions    = (const int*)d_in[5];
    float* out = (float*)d_out;

    const int B = in_sizes[0] / TLEN;   // 2048

    ppo_main<<<B, TLEN>>>(rewards, values, logits, logits_old, dones, actions);
    ppo_finalize<<<1, 1024>>>(out, B);
}

// round 3
// speedup vs baseline: 1.0246x; 1.0246x over previous
#include <cuda_runtime.h>
#include <cuda_bf16.h>

#define TLEN   1024
#define NTHR   256            // threads per block; 4 timesteps per thread
#define QUAD   4
#define NWARP  (NTHR / 32)
#define GAMMA  0.98f
#define GL     (0.98f * 0.93f)
#define EPSI   0.2f
#define MAXB   4096

__device__ float g_part[3 * MAXB];      // per-block partials (overwritten every launch)
__device__ unsigned int g_ctr = 0;      // finish ticket; reset by the finalizing block

__device__ __forceinline__ float warp_sum(float v) {
#pragma unroll
    for (int o = 16; o; o >>= 1) v += __shfl_xor_sync(0xffffffffu, v, o);
    return v;
}

__device__ __forceinline__ float pick6(int a, float e0, float e1, float e2,
                                       float e3, float e4, float e5) {
    return (a == 0) ? e0 : (a == 1) ? e1 : (a == 2) ? e2
         : (a == 3) ? e3 : (a == 4) ? e4 : e5;
}

// One block per batch row; thread tid owns timesteps [4*tid, 4*tid+3].
__global__ __launch_bounds__(NTHR) void ppo_fused(
    const float* __restrict__ rewards,
    const float* __restrict__ values,
    const float* __restrict__ logits,
    const float* __restrict__ logits_old,
    const int*   __restrict__ dones,     // jnp.bool_ widened to int32
    const int*   __restrict__ actions,
    float* __restrict__ out, int B)
{
    const int b    = blockIdx.x;
    const int tid  = threadIdx.x;
    const int lane = tid & 31;
    const int wrp  = tid >> 5;
    const int t0   = tid * QUAD;
    const long rowbase = (long)b * TLEN;

    // ---- vectorized loads: 16B-aligned per-thread bursts ----
    const float4 rq = *reinterpret_cast<const float4*>(rewards + rowbase + t0);
    const float4 vq = *reinterpret_cast<const float4*>(values  + rowbase + t0);
    const int4   dq = *reinterpret_cast<const int4*>(dones   + rowbase + t0);
    const int4   aq = *reinterpret_cast<const int4*>(actions + rowbase + t0);

    float lg[24], lo[24];
    {
        const float4* L4 = reinterpret_cast<const float4*>(logits     + (rowbase + t0) * 6);
        const float4* O4 = reinterpret_cast<const float4*>(logits_old + (rowbase + t0) * 6);
#pragma unroll
        for (int k = 0; k < 6; k++) *reinterpret_cast<float4*>(&lg[k * 4]) = L4[k];
#pragma unroll
        for (int k = 0; k < 6; k++) *reinterpret_cast<float4*>(&lo[k * 4]) = O4[k];
    }

    __shared__ float sv[NTHR];          // first value of each thread's quad
    sv[tid] = vq.x;

    const float rr[QUAD] = {rq.x, rq.y, rq.z, rq.w};
    const float vv[QUAD] = {vq.x, vq.y, vq.z, vq.w};
    const int   dd[QUAD] = {dq.x, dq.y, dq.z, dq.w};
    const int   ac[QUAD] = {aq.x, aq.y, aq.z, aq.w};

    // ---- per-timestep log-softmax gather (register-only) ----
    float lp[QUAD], lpo[QUAD];
#pragma unroll
    for (int j = 0; j < QUAD; j++) {
        const float* x = &lg[j * 6];
        float m = fmaxf(fmaxf(fmaxf(x[0], x[1]), fmaxf(x[2], x[3])), fmaxf(x[4], x[5]));
        float s = __expf(x[0]-m) + __expf(x[1]-m) + __expf(x[2]-m)
                + __expf(x[3]-m) + __expf(x[4]-m) + __expf(x[5]-m);
        lp[j] = pick6(ac[j], x[0], x[1], x[2], x[3], x[4], x[5]) - (m + __logf(s));

        const float* y = &lo[j * 6];
        float mo = fmaxf(fmaxf(fmaxf(y[0], y[1]), fmaxf(y[2], y[3])), fmaxf(y[4], y[5]));
        float so = __expf(y[0]-mo) + __expf(y[1]-mo) + __expf(y[2]-mo)
                 + __expf(y[3]-mo) + __expf(y[4]-mo) + __expf(y[5]-mo);
        lpo[j] = pick6(ac[j], y[0], y[1], y[2], y[3], y[4], y[5]) - (mo + __logf(so));
    }

    __syncthreads();
    const float vnext3 = (tid < NTHR - 1) ? sv[tid + 1] : 0.f;   // v[t0+4]

    // ---- per-timestep affine pairs: x_t = bX + aX * x_{t+1} ----
    float aR[QUAD], bR[QUAD], aA[QUAD], bA[QUAD];
#pragma unroll
    for (int j = 0; j < QUAD; j++) {
        const bool dn = dd[j] != 0;
        if (t0 + j == TLEN - 1) {                 // terminal timestep
            aR[j] = 0.f; bR[j] = dn ? rr[j] : vv[j];
            aA[j] = 0.f; bA[j] = 0.f;
        } else {
            const float vn = (j < 3) ? vv[j + 1] : vnext3;
            aR[j] = dn ? 0.f : GAMMA;  bR[j] = rr[j];
            aA[j] = dn ? 0.f : GL;
            bA[j] = rr[j] + GAMMA * (dn ? 0.f : vn) - vv[j];   // td error
        }
    }

    // ---- serial composition of the quad (maps x[t0+4] -> x[t0]) ----
    float Ar = aR[3], Br = bR[3], Aa = aA[3], Ba = bA[3];
#pragma unroll
    for (int j = 2; j >= 0; j--) {
        Br = fmaf(aR[j], Br, bR[j]);  Ar = aR[j] * Ar;
        Ba = fmaf(aA[j], Ba, bA[j]);  Aa = aA[j] * Aa;
    }

    // ---- warp-level Kogge-Stone inclusive suffix scan (both fused) ----
#pragma unroll
    for (int d2 = 1; d2 < 32; d2 <<= 1) {
        float Ar2 = __shfl_down_sync(0xffffffffu, Ar, d2);
        float Br2 = __shfl_down_sync(0xffffffffu, Br, d2);
        float Aa2 = __shfl_down_sync(0xffffffffu, Aa, d2);
        float Ba2 = __shfl_down_sync(0xffffffffu, Ba, d2);
        if (lane + d2 < 32) {
            Br = fmaf(Ar, Br2, Br);  Ar *= Ar2;
            Ba = fmaf(Aa, Ba2, Ba);  Aa *= Aa2;
        }
    }

    // in-warp exclusive (composition over threads [tid+1 .. warp_end])
    float eAr = __shfl_down_sync(0xffffffffu, Ar, 1);
    float eBr = __shfl_down_sync(0xffffffffu, Br, 1);
    float eAa = __shfl_down_sync(0xffffffffu, Aa, 1);
    float eBa = __shfl_down_sync(0xffffffffu, Ba, 1);
    if (lane == 31) { eAr = 1.f; eBr = 0.f; eAa = 1.f; eBa = 0.f; }

    // ---- cross-warp: exclusive suffix over the 8 warp aggregates ----
    __shared__ float sWa[NWARP], sWb[NWARP], sGa[NWARP], sGb[NWARP];
    __shared__ float sWR[NWARP], sWA[NWARP];      // carry values x[(w+1)*128]
    if (lane == 0) { sWa[wrp] = Ar; sWb[wrp] = Br; sGa[wrp] = Aa; sGb[wrp] = Ba; }
    __syncthreads();

    if (wrp == 0 && lane < NWARP) {
        float ga = sWa[lane], gb = sWb[lane], ha = sGa[lane], hb = sGb[lane];
#pragma unroll
        for (int d2 = 1; d2 < NWARP; d2 <<= 1) {
            float ga2 = __shfl_down_sync(0xffu, ga, d2);
            float gb2 = __shfl_down_sync(0xffu, gb, d2);
            float ha2 = __shfl_down_sync(0xffu, ha, d2);
            float hb2 = __shfl_down_sync(0xffu, hb, d2);
            if (lane + d2 < NWARP) {
                gb = fmaf(ga, gb2, gb);  ga *= ga2;
                hb = fmaf(ha, hb2, hb);  ha *= ha2;
            }
        }
        float cb = __shfl_down_sync(0xffu, gb, 1);
        float db = __shfl_down_sync(0xffu, hb, 1);
        if (lane == NWARP - 1) { cb = 0.f; db = 0.f; }
        sWR[lane] = cb;                 // x_R at (w+1)*128
        sWA[lane] = db;                 // x_A at (w+1)*128
    }
    __syncthreads();

    // thread carry: x at t0+4
    const float CR = fmaf(eAr, sWR[wrp], eBr);
    const float CA = fmaf(eAa, sWA[wrp], eBa);

    // ---- recover per-timestep values and accumulate losses ----
    float pt = 0.f, vt = 0.f, ent = 0.f;
    float xR = CR, xA = CA;
#pragma unroll
    for (int j = QUAD - 1; j >= 0; j--) {
        xR = fmaf(aR[j], xR, bR[j]);        // future return at t0+j
        xA = fmaf(aA[j], xA, bA[j]);        // GAE at t0+j
        ent += lp[j];
        const float dv = xR - vv[j];
        vt = fmaf(dv, dv, vt);
        if (t0 + j < TLEN - 1) {
            const float ratio = __expf(lp[j] - lpo[j]);
            // clip(r, 1-eps, eps) with 1-eps > eps collapses to constant eps
            pt += fminf(ratio * xA, EPSI * xA);
        }
    }

    // ---- block reduction -> per-block partials ----
    pt = warp_sum(pt); vt = warp_sum(vt); ent = warp_sum(ent);
    __shared__ float r0[NWARP], r1[NWARP], r2[NWARP];
    if (lane == 0) { r0[wrp] = pt; r1[wrp] = vt; r2[wrp] = ent; }
    __syncthreads();

    __shared__ bool s_last;
    if (tid == 0) {
        float a0 = 0.f, a1 = 0.f, a2 = 0.f;
#pragma unroll
        for (int w = 0; w < NWARP; w++) { a0 += r0[w]; a1 += r1[w]; a2 += r2[w]; }
        g_part[b]            = a0;
        g_part[MAXB + b]     = a1;
        g_part[2 * MAXB + b] = a2;
        __threadfence();
        s_last = (atomicAdd(&g_ctr, 1u) == (unsigned)(gridDim.x - 1));
    }
    __syncthreads();

    // ---- last block to finish performs the (deterministic) final reduction ----
    if (s_last) {
        float s0 = 0.f, s1 = 0.f, s2 = 0.f;
        for (int i = tid; i < B; i += NTHR) {
            s0 += g_part[i];
            s1 += g_part[MAXB + i];
            s2 += g_part[2 * MAXB + i];
        }
        s0 = warp_sum(s0); s1 = warp_sum(s1); s2 = warp_sum(s2);
        if (lane == 0) { r0[wrp] = s0; r1[wrp] = s1; r2[wrp] = s2; }
        __syncthreads();
        if (tid == 0) {
            float a0 = 0.f, a1 = 0.f, a2 = 0.f;
#pragma unroll
            for (int w = 0; w < NWARP; w++) { a0 += r0[w]; a1 += r1[w]; a2 += r2[w]; }
            const double nBT  = (double)B * TLEN;
            const double nBT1 = (double)B * (TLEN - 1);
            out[0] = (float)(-(double)a0 / nBT1);   // ppo_loss
            out[1] = (float)( (double)a1 / nBT);    // value_loss
            out[2] = (float)(-(double)a2 / nBT);    // entropy_loss
            g_ctr = 0;                              // reset for next graph replay
        }
    }
}

extern "C" void kernel_launch(void* const* d_in, const int* in_sizes, int n_in,
                              void* d_out, int out_size)
{
    const float* rewards    = (const float*)d_in[0];
    const float* values     = (const float*)d_in[1];
    const float* logits     = (const float*)d_in[2];
    const float* logits_old = (const float*)d_in[3];
    const int*   dones      = (const int*)d_in[4];
    const int*   actions    = (const int*)d_in[5];
    float* out = (float*)d_out;

    const int B = in_sizes[0] / TLEN;   // 2048

    ppo_fused<<<B, NTHR>>>(rewards, values, logits, logits_old, dones, actions, out, B);
}

// round 4
// speedup vs baseline: 1.0836x; 1.0575x over previous
#include <cuda_runtime.h>
#include <cuda_bf16.h>

#define TLEN   1024
#define NTHR   256            // threads per block
#define QUAD   4              // timesteps per thread in scan phase
#define CHUNK  256            // timesteps staged per logits chunk
#define NCHUNK (TLEN / CHUNK)
#define NWARP  (NTHR / 32)
#define GAMMA  0.98f
#define GL     (0.98f * 0.93f)
#define EPSI   0.2f
#define MAXB   4096

__device__ float g_part[3 * MAXB];      // per-block partials (overwritten every launch)
__device__ unsigned int g_ctr = 0;      // finish ticket; reset by the finalizing block

__device__ __forceinline__ float warp_sum(float v) {
#pragma unroll
    for (int o = 16; o; o >>= 1) v += __shfl_xor_sync(0xffffffffu, v, o);
    return v;
}

__device__ __forceinline__ float pick6(int a, const float* x) {
    return (a == 0) ? x[0] : (a == 1) ? x[1] : (a == 2) ? x[2]
         : (a == 3) ? x[3] : (a == 4) ? x[4] : x[5];
}

// One block per batch row b.
__global__ __launch_bounds__(NTHR, 5) void ppo_fused(
    const float* __restrict__ rewards,
    const float* __restrict__ values,
    const float* __restrict__ logits,
    const float* __restrict__ logits_old,
    const int*   __restrict__ dones,     // jnp.bool_ widened to int32
    const int*   __restrict__ actions,
    float* __restrict__ out, int B)
{
    const int b    = blockIdx.x;
    const int tid  = threadIdx.x;
    const int lane = tid & 31;
    const int wrp  = tid >> 5;
    const long rowbase = (long)b * TLEN;

    __shared__ float s_stageL[CHUNK * 6];   // 6 KB
    __shared__ float s_stageO[CHUNK * 6];   // 6 KB
    __shared__ float s_ratio[TLEN];         // 4 KB
    __shared__ float sv[NTHR];
    __shared__ float r0[NWARP], r1[NWARP], r2[NWARP];
    __shared__ bool  s_last;

    // ================= Phase 1: logits streaming (coalesced) =================
    float ent = 0.f;
#pragma unroll 1
    for (int c = 0; c < NCHUNK; c++) {
        const long fbase = (rowbase + (long)c * CHUNK) * 6;   // float offset, 16B-aligned
        const float4* L4 = reinterpret_cast<const float4*>(logits     + fbase);
        const float4* O4 = reinterpret_cast<const float4*>(logits_old + fbase);
        float4* SL = reinterpret_cast<float4*>(s_stageL);
        float4* SO = reinterpret_cast<float4*>(s_stageO);
        // 256 ts * 6 floats = 1536 floats = 384 float4 per array
        SL[tid] = L4[tid];
        SO[tid] = O4[tid];
        if (tid < 128) {
            SL[NTHR + tid] = L4[NTHR + tid];
            SO[NTHR + tid] = O4[NTHR + tid];
        }
        __syncthreads();

        const int t = c * CHUNK + tid;           // this thread's timestep
        const int a = actions[rowbase + t];      // coalesced 4B

        const float* x = &s_stageL[tid * 6];
        float m = fmaxf(fmaxf(fmaxf(x[0], x[1]), fmaxf(x[2], x[3])), fmaxf(x[4], x[5]));
        float s = __expf(x[0]-m) + __expf(x[1]-m) + __expf(x[2]-m)
                + __expf(x[3]-m) + __expf(x[4]-m) + __expf(x[5]-m);
        const float lp = pick6(a, x) - (m + __logf(s));

        const float* y = &s_stageO[tid * 6];
        float mo = fmaxf(fmaxf(fmaxf(y[0], y[1]), fmaxf(y[2], y[3])), fmaxf(y[4], y[5]));
        float so = __expf(y[0]-mo) + __expf(y[1]-mo) + __expf(y[2]-mo)
                 + __expf(y[3]-mo) + __expf(y[4]-mo) + __expf(y[5]-mo);
        const float lpo = pick6(a, y) - (mo + __logf(so));

        ent += lp;
        s_ratio[t] = __expf(lp - lpo);           // unused at t = TLEN-1
        __syncthreads();                         // stage buffers reused next chunk
    }

    // ================= Phase 2: dual affine suffix scan =================
    const int t0 = tid * QUAD;
    const float4 rq = *reinterpret_cast<const float4*>(rewards + rowbase + t0);
    const float4 vq = *reinterpret_cast<const float4*>(values  + rowbase + t0);
    const int4   dq = *reinterpret_cast<const int4*>(dones    + rowbase + t0);

    sv[tid] = vq.x;
    __syncthreads();
    const float vnext3 = (tid < NTHR - 1) ? sv[tid + 1] : 0.f;   // v[t0+4]

    const float rr[QUAD] = {rq.x, rq.y, rq.z, rq.w};
    const float vv[QUAD] = {vq.x, vq.y, vq.z, vq.w};
    const int   dd[QUAD] = {dq.x, dq.y, dq.z, dq.w};

    // x_t = bX + aX * x_{t+1}; suffix-compose (a,b)⊕(a2,b2) = (a*a2, b + a*b2)
    float aR[QUAD], bR[QUAD], aA[QUAD], bA[QUAD];
#pragma unroll
    for (int j = 0; j < QUAD; j++) {
        const bool dn = dd[j] != 0;
        if (t0 + j == TLEN - 1) {                 // terminal timestep
            aR[j] = 0.f; bR[j] = dn ? rr[j] : vv[j];
            aA[j] = 0.f; bA[j] = 0.f;
        } else {
            const float vn = (j < 3) ? vv[j + 1] : vnext3;
            aR[j] = dn ? 0.f : GAMMA;  bR[j] = rr[j];
            aA[j] = dn ? 0.f : GL;
            bA[j] = rr[j] + GAMMA * (dn ? 0.f : vn) - vv[j];   // td error
        }
    }

    // serial composition of the quad (maps x[t0+4] -> x[t0])
    float Ar = aR[3], Br = bR[3], Aa = aA[3], Ba = bA[3];
#pragma unroll
    for (int j = 2; j >= 0; j--) {
        Br = fmaf(aR[j], Br, bR[j]);  Ar = aR[j] * Ar;
        Ba = fmaf(aA[j], Ba, bA[j]);  Aa = aA[j] * Aa;
    }

    // warp-level Kogge-Stone inclusive suffix scan (both recurrences fused)
#pragma unroll
    for (int d2 = 1; d2 < 32; d2 <<= 1) {
        float Ar2 = __shfl_down_sync(0xffffffffu, Ar, d2);
        float Br2 = __shfl_down_sync(0xffffffffu, Br, d2);
        float Aa2 = __shfl_down_sync(0xffffffffu, Aa, d2);
        float Ba2 = __shfl_down_sync(0xffffffffu, Ba, d2);
        if (lane + d2 < 32) {
            Br = fmaf(Ar, Br2, Br);  Ar *= Ar2;
            Ba = fmaf(Aa, Ba2, Ba);  Aa *= Aa2;
        }
    }

    // in-warp exclusive (composition over threads [tid+1 .. warp end])
    float eAr = __shfl_down_sync(0xffffffffu, Ar, 1);
    float eBr = __shfl_down_sync(0xffffffffu, Br, 1);
    float eAa = __shfl_down_sync(0xffffffffu, Aa, 1);
    float eBa = __shfl_down_sync(0xffffffffu, Ba, 1);
    if (lane == 31) { eAr = 1.f; eBr = 0.f; eAa = 1.f; eBa = 0.f; }

    // cross-warp: exclusive suffix over the 8 warp aggregates
    __shared__ float sWa[NWARP], sWb[NWARP], sGa[NWARP], sGb[NWARP];
    __shared__ float sWR[NWARP], sWA[NWARP];      // carry values x[(w+1)*128]
    if (lane == 0) { sWa[wrp] = Ar; sWb[wrp] = Br; sGa[wrp] = Aa; sGb[wrp] = Ba; }
    __syncthreads();

    if (wrp == 0 && lane < NWARP) {
        float ga = sWa[lane], gb = sWb[lane], ha = sGa[lane], hb = sGb[lane];
#pragma unroll
        for (int d2 = 1; d2 < NWARP; d2 <<= 1) {
            float ga2 = __shfl_down_sync(0xffu, ga, d2);
            float gb2 = __shfl_down_sync(0xffu, gb, d2);
            float ha2 = __shfl_down_sync(0xffu, ha, d2);
            float hb2 = __shfl_down_sync(0xffu, hb, d2);
            if (lane + d2 < NWARP) {
                gb = fmaf(ga, gb2, gb);  ga *= ga2;
                hb = fmaf(ha, hb2, hb);  ha *= ha2;
            }
        }
        float cb = __shfl_down_sync(0xffu, gb, 1);
        float db = __shfl_down_sync(0xffu, hb, 1);
        if (lane == NWARP - 1) { cb = 0.f; db = 0.f; }
        sWR[lane] = cb;                 // x_R at (w+1)*128
        sWA[lane] = db;                 // x_A at (w+1)*128
    }
    __syncthreads();

    // thread carry: x at t0+4
    float xR = fmaf(eAr, sWR[wrp], eBr);
    float xA = fmaf(eAa, sWA[wrp], eBa);

    // ================= Phase 3: losses =================
    const float4 rt4 = *reinterpret_cast<const float4*>(&s_ratio[t0]);
    const float rat[QUAD] = {rt4.x, rt4.y, rt4.z, rt4.w};

    float pt = 0.f, vt = 0.f;
#pragma unroll
    for (int j = QUAD - 1; j >= 0; j--) {
        xR = fmaf(aR[j], xR, bR[j]);        // future return at t0+j
        xA = fmaf(aA[j], xA, bA[j]);        // GAE at t0+j
        const float dv = xR - vv[j];
        vt = fmaf(dv, dv, vt);
        if (t0 + j < TLEN - 1) {
            // clip(r, 1-eps, eps) with 1-eps > eps collapses to constant eps
            pt += fminf(rat[j] * xA, EPSI * xA);
        }
    }

    // block reduction -> per-block partials
    pt = warp_sum(pt); vt = warp_sum(vt); ent = warp_sum(ent);
    if (lane == 0) { r0[wrp] = pt; r1[wrp] = vt; r2[wrp] = ent; }
    __syncthreads();

    if (tid == 0) {
        float a0 = 0.f, a1 = 0.f, a2 = 0.f;
#pragma unroll
        for (int w = 0; w < NWARP; w++) { a0 += r0[w]; a1 += r1[w]; a2 += r2[w]; }
        g_part[b]            = a0;
        g_part[MAXB + b]     = a1;
        g_part[2 * MAXB + b] = a2;
        __threadfence();
        s_last = (atomicAdd(&g_ctr, 1u) == (unsigned)(gridDim.x - 1));
    }
    __syncthreads();

    // last block to finish performs the (deterministic) final reduction
    if (s_last) {
        float s0 = 0.f, s1 = 0.f, s2 = 0.f;
        for (int i = tid; i < B; i += NTHR) {
            s0 += g_part[i];
            s1 += g_part[MAXB + i];
            s2 += g_part[2 * MAXB + i];
        }
        s0 = warp_sum(s0); s1 = warp_sum(s1); s2 = warp_sum(s2);
        if (lane == 0) { r0[wrp] = s0; r1[wrp] = s1; r2[wrp] = s2; }
        __syncthreads();
        if (tid == 0) {
            float a0 = 0.f, a1 = 0.f, a2 = 0.f;
#pragma unroll
            for (int w = 0; w < NWARP; w++) { a0 += r0[w]; a1 += r1[w]; a2 += r2[w]; }
            const double nBT  = (double)B * TLEN;
            const double nBT1 = (double)B * (TLEN - 1);
            out[0] = (float)(-(double)a0 / nBT1);   // ppo_loss
            out[1] = (float)( (double)a1 / nBT);    // value_loss
            out[2] = (float)(-(double)a2 / nBT);    // entropy_loss
            g_ctr = 0;                              // reset for next graph replay
        }
    }
}

extern "C" void kernel_launch(void* const* d_in, const int* in_sizes, int n_in,
                              void* d_out, int out_size)
{
    const float* rewards    = (const float*)d_in[0];
    const float* values     = (const float*)d_in[1];
    const float* logits     = (const float*)d_in[2];
    const float* logits_old = (const float*)d_in[3];
    const int*   dones      = (const int*)d_in[4];
    const int*   actions    = (const int*)d_in[5];
    float* out = (float*)d_out;

    const int B = in_sizes[0] / TLEN;   // 2048

    ppo_fused<<<B, NTHR>>>(rewards, values, logits, logits_old, dones, actions, out, B);
}

// round 6
// speedup vs baseline: 1.1754x; 1.0848x over previous
#include <cuda_runtime.h>
#include <cuda_bf16.h>
#include <cstdint>

#define TLEN   1024
#define NTHR   256            // threads per block
#define QUAD   4              // timesteps per thread in scan phase
#define CHUNK  256            // timesteps per staged logits chunk
#define NCHUNK (TLEN / CHUNK) // 4
#define NBUF   3              // staging ring depth
#define F4_PER_CHUNK 768      // (256 ts * 6 fl * 2 arrays) / 4
#define NWARP  (NTHR / 32)
#define GAMMA  0.98f
#define GL     (0.98f * 0.93f)
#define EPSI   0.2f
#define MAXB   4096

__device__ float g_part[3 * MAXB];      // per-block partials (overwritten every launch)
__device__ unsigned int g_ctr = 0;      // finish ticket; reset by finalizing block

__device__ __forceinline__ float warp_sum(float v) {
#pragma unroll
    for (int o = 16; o; o >>= 1) v += __shfl_xor_sync(0xffffffffu, v, o);
    return v;
}

__device__ __forceinline__ float pick6(int a, const float* x) {
    return (a == 0) ? x[0] : (a == 1) ? x[1] : (a == 2) ? x[2]
         : (a == 3) ? x[3] : (a == 4) ? x[4] : x[5];
}

__device__ __forceinline__ void cp16(void* smem_dst, const void* gmem_src) {
    unsigned int s = (unsigned int)__cvta_generic_to_shared(smem_dst);
    asm volatile("cp.async.cg.shared.global [%0], [%1], 16;\n"
                 :: "r"(s), "l"(gmem_src));
}
#define CP_COMMIT()  asm volatile("cp.async.commit_group;\n" ::: "memory")
#define CP_WAIT(n)   asm volatile("cp.async.wait_group %0;\n" :: "n"(n) : "memory")

// One block per batch row b.
__global__ __launch_bounds__(NTHR, 4) void ppo_fused(
    const float* __restrict__ rewards,
    const float* __restrict__ values,
    const float* __restrict__ logits,
    const float* __restrict__ logits_old,
    const int*   __restrict__ dones,     // jnp.bool_ widened to int32
    const int*   __restrict__ actions,
    float* __restrict__ out, int B)
{
    const int b    = blockIdx.x;
    const int tid  = threadIdx.x;
    const int lane = tid & 31;
    const int wrp  = tid >> 5;
    const long rowbase = (long)b * TLEN;

    // ring buffer: per chunk, float4 [0,384) = logits, [384,768) = logits_old
    __shared__ float4 s_stage[NBUF][F4_PER_CHUNK];     // 36 KB
    __shared__ float  s_ratio[TLEN];                   // 4 KB
    __shared__ float  sv[NTHR];
    __shared__ float  sWa[NWARP], sWb[NWARP], sGa[NWARP], sGb[NWARP];
    __shared__ float  sWR[NWARP], sWA[NWARP];
    __shared__ float  r0[NWARP], r1[NWARP], r2[NWARP];
    __shared__ bool   s_last;

    // ---- issue helper (3 cp.async of 16B per thread per chunk) ----
    auto issue_chunk = [&](int c) {
        const float4* L4 = reinterpret_cast<const float4*>(logits     + (rowbase + (long)c * CHUNK) * 6);
        const float4* O4 = reinterpret_cast<const float4*>(logits_old + (rowbase + (long)c * CHUNK) * 6);
        float4* S = s_stage[c % NBUF];
        cp16(S + tid, L4 + tid);                               // [0,256)
        const int i1 = 256 + tid;                              // [256,512)
        cp16(S + i1, (i1 < 384) ? (L4 + i1) : (O4 + (i1 - 384)));
        const int i2 = 512 + tid;                              // [512,768)
        cp16(S + i2, O4 + (i2 - 384));
        CP_COMMIT();
    };

    // ---- prologue: async-issue chunks 0,1; prefetch phase-2 operands ----
    issue_chunk(0);
    issue_chunk(1);

    const int t0 = tid * QUAD;
    const float4 rq = *reinterpret_cast<const float4*>(rewards + rowbase + t0);
    const float4 vq = *reinterpret_cast<const float4*>(values  + rowbase + t0);
    const int4   dq = *reinterpret_cast<const int4*>(dones    + rowbase + t0);
    int ac[NCHUNK];
#pragma unroll
    for (int c = 0; c < NCHUNK; c++) ac[c] = actions[rowbase + c * CHUNK + tid];

    // ================= Phase 1: pipelined log-softmax streaming =================
    float ent = 0.f;
#pragma unroll
    for (int c = 0; c < NCHUNK; c++) {
        if (c < NCHUNK - 1) { CP_WAIT(1); } else { CP_WAIT(0); }
        __syncthreads();                       // data visible; old buffer free
        if (c + 2 < NCHUNK) issue_chunk(c + 2);

        const float* bpf = reinterpret_cast<const float*>(s_stage[c % NBUF]);
        const float* x = bpf + tid * 6;                 // new logits, ts c*CHUNK+tid
        const float* y = bpf + CHUNK * 6 + tid * 6;     // old logits

        float m = fmaxf(fmaxf(fmaxf(x[0], x[1]), fmaxf(x[2], x[3])), fmaxf(x[4], x[5]));
        float s = __expf(x[0]-m) + __expf(x[1]-m) + __expf(x[2]-m)
                + __expf(x[3]-m) + __expf(x[4]-m) + __expf(x[5]-m);
        const float lp = pick6(ac[c], x) - (m + __logf(s));

        float mo = fmaxf(fmaxf(fmaxf(y[0], y[1]), fmaxf(y[2], y[3])), fmaxf(y[4], y[5]));
        float so = __expf(y[0]-mo) + __expf(y[1]-mo) + __expf(y[2]-mo)
                 + __expf(y[3]-mo) + __expf(y[4]-mo) + __expf(y[5]-mo);
        const float lpo = pick6(ac[c], y) - (mo + __logf(so));

        ent += lp;
        s_ratio[c * CHUNK + tid] = __expf(lp - lpo);    // unused at t = TLEN-1
    }

    // ================= Phase 2: dual affine suffix scan =================
    sv[tid] = vq.x;
    __syncthreads();                                    // also orders s_ratio writes
    const float vnext3 = (tid < NTHR - 1) ? sv[tid + 1] : 0.f;   // v[t0+4]

    const float rr[QUAD] = {rq.x, rq.y, rq.z, rq.w};
    const float vv[QUAD] = {vq.x, vq.y, vq.z, vq.w};
    const int   dd[QUAD] = {dq.x, dq.y, dq.z, dq.w};

    // x_t = bX + aX * x_{t+1}; suffix-compose (a,b)⊕(a2,b2) = (a*a2, b + a*b2)
    float aR[QUAD], bR[QUAD], aA[QUAD], bA[QUAD];
#pragma unroll
    for (int j = 0; j < QUAD; j++) {
        const bool dn = dd[j] != 0;
        if (t0 + j == TLEN - 1) {                 // terminal timestep
            aR[j] = 0.f; bR[j] = dn ? rr[j] : vv[j];
            aA[j] = 0.f; bA[j] = 0.f;
        } else {
            const float vn = (j < 3) ? vv[j + 1] : vnext3;
            aR[j] = dn ? 0.f : GAMMA;  bR[j] = rr[j];
            aA[j] = dn ? 0.f : GL;
            bA[j] = rr[j] + GAMMA * (dn ? 0.f : vn) - vv[j];   // td error
        }
    }

    // serial composition of the quad (maps x[t0+4] -> x[t0])
    float Ar = aR[3], Br = bR[3], Aa = aA[3], Ba = bA[3];
#pragma unroll
    for (int j = 2; j >= 0; j--) {
        Br = fmaf(aR[j], Br, bR[j]);  Ar = aR[j] * Ar;
        Ba = fmaf(aA[j], Ba, bA[j]);  Aa = aA[j] * Aa;
    }

    // warp-level Kogge-Stone inclusive suffix scan (both recurrences fused)
#pragma unroll
    for (int d2 = 1; d2 < 32; d2 <<= 1) {
        float Ar2 = __shfl_down_sync(0xffffffffu, Ar, d2);
        float Br2 = __shfl_down_sync(0xffffffffu, Br, d2);
        float Aa2 = __shfl_down_sync(0xffffffffu, Aa, d2);
        float Ba2 = __shfl_down_sync(0xffffffffu, Ba, d2);
        if (lane + d2 < 32) {
            Br = fmaf(Ar, Br2, Br);  Ar *= Ar2;
            Ba = fmaf(Aa, Ba2, Ba);  Aa *= Aa2;
        }
    }

    // in-warp exclusive (composition over threads [tid+1 .. warp end])
    float eAr = __shfl_down_sync(0xffffffffu, Ar, 1);
    float eBr = __shfl_down_sync(0xffffffffu, Br, 1);
    float eAa = __shfl_down_sync(0xffffffffu, Aa, 1);
    float eBa = __shfl_down_sync(0xffffffffu, Ba, 1);
    if (lane == 31) { eAr = 1.f; eBr = 0.f; eAa = 1.f; eBa = 0.f; }

    // cross-warp: exclusive suffix over the 8 warp aggregates
    if (lane == 0) { sWa[wrp] = Ar; sWb[wrp] = Br; sGa[wrp] = Aa; sGb[wrp] = Ba; }
    __syncthreads();

    if (wrp == 0 && lane < NWARP) {
        float ga = sWa[lane], gb = sWb[lane], ha = sGa[lane], hb = sGb[lane];
#pragma unroll
        for (int d2 = 1; d2 < NWARP; d2 <<= 1) {
            float ga2 = __shfl_down_sync(0xffu, ga, d2);
            float gb2 = __shfl_down_sync(0xffu, gb, d2);
            float ha2 = __shfl_down_sync(0xffu, ha, d2);
            float hb2 = __shfl_down_sync(0xffu, hb, d2);
            if (lane + d2 < NWARP) {
                gb = fmaf(ga, gb2, gb);  ga *= ga2;
                hb = fmaf(ha, hb2, hb);  ha *= ha2;
            }
        }
        float cb = __shfl_down_sync(0xffu, gb, 1);
        float db = __shfl_down_sync(0xffu, hb, 1);
        if (lane == NWARP - 1) { cb = 0.f; db = 0.f; }
        sWR[lane] = cb;                 // x_R at (w+1)*128
        sWA[lane] = db;                 // x_A at (w+1)*128
    }
    __syncthreads();

    // thread carry: x at t0+4
    float xR = fmaf(eAr, sWR[wrp], eBr);
    float xA = fmaf(eAa, sWA[wrp], eBa);

    // ================= Phase 3: losses =================
    const float4 rt4 = *reinterpret_cast<const float4*>(&s_ratio[t0]);
    const float rat[QUAD] = {rt4.x, rt4.y, rt4.z, rt4.w};

    float pt = 0.f, vt = 0.f;
#pragma unroll
    for (int j = QUAD - 1; j >= 0; j--) {
        xR = fmaf(aR[j], xR, bR[j]);        // future return at t0+j
        xA = fmaf(aA[j], xA, bA[j]);        // GAE at t0+j
        const float dv = xR - vv[j];
        vt = fmaf(dv, dv, vt);
        if (t0 + j < TLEN - 1) {
            // clip(r, 1-eps, eps) with 1-eps > eps collapses to constant eps
            pt += fminf(rat[j] * xA, EPSI * xA);
        }
    }

    // block reduction -> per-block partials
    pt = warp_sum(pt); vt = warp_sum(vt); ent = warp_sum(ent);
    if (lane == 0) { r0[wrp] = pt; r1[wrp] = vt; r2[wrp] = ent; }
    __syncthreads();

    if (tid == 0) {
        float a0 = 0.f, a1 = 0.f, a2 = 0.f;
#pragma unroll
        for (int w = 0; w < NWARP; w++) { a0 += r0[w]; a1 += r1[w]; a2 += r2[w]; }
        g_part[b]            = a0;
        g_part[MAXB + b]     = a1;
        g_part[2 * MAXB + b] = a2;
        __threadfence();
        s_last = (atomicAdd(&g_ctr, 1u) == (unsigned)(gridDim.x - 1));
    }
    __syncthreads();

    // last block to finish performs the (deterministic) final reduction
    if (s_last) {
        float s0 = 0.f, s1 = 0.f, s2 = 0.f;
        for (int i = tid; i < B; i += NTHR) {
            s0 += g_part[i];
            s1 += g_part[MAXB + i];
            s2 += g_part[2 * MAXB + i];
        }
        s0 = warp_sum(s0); s1 = warp_sum(s1); s2 = warp_sum(s2);
        if (lane == 0) { r0[wrp] = s0; r1[wrp] = s1; r2[wrp] = s2; }
        __syncthreads();
        if (tid == 0) {
            float a0 = 0.f, a1 = 0.f, a2 = 0.f;
#pragma unroll
            for (int w = 0; w < NWARP; w++) { a0 += r0[w]; a1 += r1[w]; a2 += r2[w]; }
            const double nBT  = (double)B * TLEN;
            const double nBT1 = (double)B * (TLEN - 1);
            out[0] = (float)(-(double)a0 / nBT1);   // ppo_loss
            out[1] = (float)( (double)a1 / nBT);    // value_loss
            out[2] = (float)(-(double)a2 / nBT);    // entropy_loss
            g_ctr = 0;                              // reset for next graph replay
        }
    }
}

extern "C" void kernel_launch(void* const* d_in, const int* in_sizes, int n_in,
                              void* d_out, int out_size)
{
    const float* rewards    = (const float*)d_in[0];
    const float* values     = (const float*)d_in[1];
    const float* logits     = (const float*)d_in[2];
    const float* logits_old = (const float*)d_in[3];
    const int*   dones      = (const int*)d_in[4];
    const int*   actions    = (const int*)d_in[5];
    float* out = (float*)d_out;

    const int B = in_sizes[0] / TLEN;   // 2048

    ppo_fused<<<B, NTHR>>>(rewards, values, logits, logits_old, dones, actions, out, B);
}